// round 15
// baseline (speedup 1.0000x reference)
#include <cuda_runtime.h>
#include <math.h>

#define BB 2
#define HH 720
#define WW 1280
#define HW (HH*WW)
#define NPIX (BB*HW)
#define EPSF 1e-7f

// Scratch: splat accumulators [dir][b][pixel][4ch]  (~59 MB)
__device__ __align__(16) float g_acc[(size_t)2 * BB * HW * 4];

// ---------------------------------------------------------------------------
// Splat kernel, ONE direction per launch (1 px/thread — measured REDG floor).
// ---------------------------------------------------------------------------
__global__ void __launch_bounds__(256) splat_dir_kernel(
    const float* __restrict__ img, const float* __restrict__ fl,
    const float* __restrict__ zz, float4* __restrict__ accBase)
{
    int i = blockIdx.x * blockDim.x + threadIdx.x;
    if (i >= NPIX) return;
    int b = i / HW;
    int p = i - b * HW;
    int y = p / WW;
    int x = p - y * WW;

    float fx = (float)x + 0.5f * fl[(size_t)(b * 2 + 1) * HW + p];
    float fy = (float)y + 0.5f * fl[(size_t)(b * 2 + 0) * HW + p];
    float w  = __expf(zz[(size_t)b * HW + p]);
    float vr = img[(size_t)(b * 3 + 0) * HW + p] * w;
    float vg = img[(size_t)(b * 3 + 1) * HW + p] * w;
    float vb = img[(size_t)(b * 3 + 2) * HW + p] * w;

    float x0f = floorf(fx), y0f = floorf(fy);
    int ix0 = (int)x0f, iy0 = (int)y0f;
    float ax = fx - x0f, ay = fy - y0f;

    float4* acc = accBase + (size_t)b * HW;
#pragma unroll
    for (int cy = 0; cy < 2; ++cy) {
        int ty = iy0 + cy;
        if ((unsigned)ty >= (unsigned)HH) continue;
        float wy = cy ? ay : (1.0f - ay);
#pragma unroll
        for (int cx = 0; cx < 2; ++cx) {
            int tx = ix0 + cx;
            if ((unsigned)tx >= (unsigned)WW) continue;
            float wt = wy * (cx ? ax : (1.0f - ax));
            atomicAdd(acc + ((size_t)ty * WW + tx),
                      make_float4(vr * wt, vg * wt, vb * wt, w * wt));
        }
    }
}

// ---------------------------------------------------------------------------
// Flow channels (12-15): out = 0.5 * flow. DRAM-bound; hidden under splats.
// ---------------------------------------------------------------------------
#define FQ (BB * 2 * HW / 4)
__global__ void __launch_bounds__(256) flow_copy_kernel(
    const float4* __restrict__ f0, const float4* __restrict__ f1,
    float4* __restrict__ out)
{
    int i = blockIdx.x * blockDim.x + threadIdx.x;
    if (i >= FQ) return;
    const int CH4 = HW / 4;
    int b = i / (2 * CH4);
    int rem = i - b * (2 * CH4);
    int c = rem / CH4;
    int p4 = rem - c * CH4;

    float4 q0 = __ldcs(f0 + i);
    float4 q1 = __ldcs(f1 + i);
    float4 h0 = make_float4(0.5f*q0.x, 0.5f*q0.y, 0.5f*q0.z, 0.5f*q0.w);
    float4 h1 = make_float4(0.5f*q1.x, 0.5f*q1.y, 0.5f*q1.z, 0.5f*q1.w);
    __stcs(out + (size_t)(b * 18 + 12 + c) * CH4 + p4, h0);
    __stcs(out + (size_t)(b * 18 + 14 + c) * CH4 + p4, h1);
}

// ---------------------------------------------------------------------------
// Fused normalize + morphological open + compose.
// 64x16 px tile, 32x16 threads, 2 px/thread (x-pairs), float2 stores.
// BOTH masks packed per smem entry as float2 -> one LDS.64/STS.64 per tap
// (halves shared lanes). Buffer overlay across stage lifetimes:
//   BufA: s_in (st 1-2) -> s_er (st 3-4);  BufB: s_hm (st 2-3) -> s_hx (4-5).
// 38.9KB dyn smem, 4 blocks/SM, regs clamped to 32.
// ---------------------------------------------------------------------------
#define TPX 64
#define TBX 32
#define TTY 16
#define RMAX 4
#define NT (TBX * TTY)   // 512

#define NIN_E ((TTY + 4 * RMAX) * (TPX + 4 * RMAX))  // 2560 float2
#define NHM_E ((TTY + 4 * RMAX) * (TPX + 2 * RMAX))  // 2304 float2
#define DYN_SMEM_BYTES ((NIN_E + NHM_E) * (int)sizeof(float2))  // 38912 B

__device__ __forceinline__ float2 fmin2(float2 a, float2 b) {
    return make_float2(fminf(a.x, b.x), fminf(a.y, b.y));
}
__device__ __forceinline__ float2 fmax2(float2 a, float2 b) {
    return make_float2(fmaxf(a.x, b.x), fmaxf(a.y, b.y));
}

template<int R>
__device__ __forceinline__ void open_body(
    float2* __restrict__ BufA, float2* __restrict__ BufB,
    float* __restrict__ out)
{
    constexpr int INW = TPX + 4 * R;
    constexpr int INH = TTY + 4 * R;
    constexpr int HMW = TPX + 2 * R;   // even
    constexpr int EH  = TTY + 2 * R;   // even
    constexpr int WIN = 2 * R;

    const float PINF = __int_as_float(0x7f800000);
    const float NINF = __int_as_float(0xff800000);

    int b  = blockIdx.z;
    int ox = blockIdx.x * TPX;
    int oy = blockIdx.y * TTY;
    int tid = threadIdx.y * TBX + threadIdx.x;
    int txx = threadIdx.x, tyy = threadIdx.y;

    // s_in/s_er share BufA; s_hm/s_hx share BufB. Each entry = (m0, m1).
#define S_IN(iy, ix) BufA[(iy) * INW + (ix)]
#define S_ER(ey, hx) BufA[(ey) * HMW + (hx)]
#define S_HM(iy, hx) BufB[(iy) * HMW + (hx)]
#define S_HX(ey, xx) BufB[(ey) * TPX + (xx)]

    int gx0 = ox + 2 * txx;
    int gy  = oy + tyy;
    size_t p0 = (size_t)gy * WW + gx0;

    const float* w0 = g_acc + ((size_t)(0 * BB + b) * HW << 2) + 3;
    const float* w1 = g_acc + ((size_t)(1 * BB + b) * HW << 2) + 3;

    // Stage 1a: center w values (2 px, both masks packed)
    {
        int cy = tyy + 2 * R, cx = 2 * txx + 2 * R;
        S_IN(cy, cx)     = make_float2(w0[p0 << 2],       w1[p0 << 2]);
        S_IN(cy, cx + 1) = make_float2(w0[(p0 + 1) << 2], w1[(p0 + 1) << 2]);
    }

    // Stage 1b: halo RING only; +inf outside image (erosion pad)
    if (R > 0) {
        for (int idx = tid; idx < INH * INW; idx += NT) {
            int iy = idx / INW;
            int ix = idx - iy * INW;
            if ((unsigned)(iy - 2 * R) < (unsigned)TTY &&
                (unsigned)(ix - 2 * R) < (unsigned)TPX) continue;
            int hy = oy - 2 * R + iy;
            int hx = ox - 2 * R + ix;
            float v0 = PINF, v1 = PINF;
            if ((unsigned)hy < (unsigned)HH && (unsigned)hx < (unsigned)WW) {
                size_t o = ((size_t)hy * WW + hx) << 2;
                v0 = w0[o];
                v1 = w1[o];
            }
            S_IN(iy, ix) = make_float2(v0, v1);
        }
    }
    __syncthreads();

    // Stage 2: horizontal min, paired outputs (reads s_in, writes s_hm)
    {
        constexpr int HMW2 = HMW / 2;
        for (int idx = tid; idx < INH * HMW2; idx += NT) {
            int iy = idx / HMW2;
            int hx = (idx - iy * HMW2) * 2;
            float2 c = S_IN(iy, hx + 1);
#pragma unroll
            for (int dd = 2; dd <= WIN; ++dd)
                c = fmin2(c, S_IN(iy, hx + dd));
            S_HM(iy, hx)     = fmin2(S_IN(iy, hx), c);
            S_HM(iy, hx + 1) = fmin2(c, S_IN(iy, hx + WIN + 1));
        }
    }
    __syncthreads();   // s_in dead -> BufA reusable as s_er

    // Stage 3: vertical min -> erosion (reads s_hm, writes s_er); OOB -> -inf
    {
        constexpr int EH2 = EH / 2;
        for (int idx = tid; idx < EH2 * HMW; idx += NT) {
            int ep = idx / HMW;
            int hx = idx - ep * HMW;
            int ey = ep * 2;
            int hgx = ox - R + hx;
            bool colok = (unsigned)hgx < (unsigned)WW;
            int hy0 = oy - R + ey;
            float2 c = S_HM(ey + 1, hx);
#pragma unroll
            for (int dd = 2; dd <= WIN; ++dd)
                c = fmin2(c, S_HM(ey + dd, hx));
            bool ok0 = colok && ((unsigned)hy0 < (unsigned)HH);
            bool ok1 = colok && ((unsigned)(hy0 + 1) < (unsigned)HH);
            float2 ninf2 = make_float2(NINF, NINF);
            S_ER(ey, hx)     = ok0 ? fmin2(S_HM(ey, hx), c) : ninf2;
            S_ER(ey + 1, hx) = ok1 ? fmin2(c, S_HM(ey + WIN + 1, hx)) : ninf2;
        }
    }
    __syncthreads();   // s_hm dead -> BufB reusable as s_hx

    // Stage 4: horizontal max (reads s_er, writes s_hx)
    {
        constexpr int TPX2 = TPX / 2;
        for (int idx = tid; idx < EH * TPX2; idx += NT) {
            int ey = idx / TPX2;
            int xx = (idx - ey * TPX2) * 2;
            float2 c = S_ER(ey, xx + 1);
#pragma unroll
            for (int dd = 2; dd <= WIN; ++dd)
                c = fmax2(c, S_ER(ey, xx + dd));
            S_HX(ey, xx)     = fmax2(S_ER(ey, xx), c);
            S_HX(ey, xx + 1) = fmax2(c, S_ER(ey, xx + WIN + 1));
        }
    }
    __syncthreads();

    // Stage 5: vertical max; f(w)=w/(w+eps); normalize centers; compose.
    {
        float2 wA = S_HX(tyy, 2 * txx);        // (m0, m1) at px a
        float2 wB = S_HX(tyy, 2 * txx + 1);    // (m0, m1) at px b
#pragma unroll
        for (int dd = 1; dd <= WIN; ++dd) {
            wA = fmax2(wA, S_HX(tyy + dd, 2 * txx));
            wB = fmax2(wB, S_HX(tyy + dd, 2 * txx + 1));
        }
        float m01a = wA.x / (wA.x + EPSF), m01b = wB.x / (wB.x + EPSF);
        float m10a = wA.y / (wA.y + EPSF), m10b = wB.y / (wB.y + EPSF);

        const float4* acc0 = reinterpret_cast<const float4*>(g_acc) + (size_t)(0 * BB + b) * HW;
        const float4* acc1 = reinterpret_cast<const float4*>(g_acc) + (size_t)(1 * BB + b) * HW;
        float4 a0a = acc0[p0], a0b = acc0[p0 + 1];
        float4 a1a = acc1[p0], a1b = acc1[p0 + 1];
        float i0a = 1.0f / (a0a.w + EPSF), i0b = 1.0f / (a0b.w + EPSF);
        float i1a = 1.0f / (a1a.w + EPSF), i1b = 1.0f / (a1b.w + EPSF);

        float f01r0 = a0a.x * i0a, f01r1 = a0b.x * i0b;
        float f01g0 = a0a.y * i0a, f01g1 = a0b.y * i0b;
        float f01b0 = a0a.z * i0a, f01b1 = a0b.z * i0b;
        float f10r0 = a1a.x * i1a, f10r1 = a1b.x * i1b;
        float f10g0 = a1a.y * i1a, f10g1 = a1b.y * i1b;
        float f10b0 = a1a.z * i1a, f10b1 = a1b.z * i1b;

        float* ob = out + (size_t)b * 18 * HW;
#define ST2(c, v0, v1) __stcs(reinterpret_cast<float2*>(&ob[(size_t)(c) * HW + p0]), make_float2(v0, v1))
        ST2(0,  m01a * f01r0 + (1.0f - m01a) * f10r0, m01b * f01r1 + (1.0f - m01b) * f10r1);
        ST2(1,  m01a * f01g0 + (1.0f - m01a) * f10g0, m01b * f01g1 + (1.0f - m01b) * f10g1);
        ST2(2,  m01a * f01b0 + (1.0f - m01a) * f10b0, m01b * f01b1 + (1.0f - m01b) * f10b1);
        ST2(3,  m10a * f10r0 + (1.0f - m10a) * f01r0, m10b * f10r1 + (1.0f - m10b) * f01r1);
        ST2(4,  m10a * f10g0 + (1.0f - m10a) * f01g0, m10b * f10g1 + (1.0f - m10b) * f01g1);
        ST2(5,  m10a * f10b0 + (1.0f - m10a) * f01b0, m10b * f10b1 + (1.0f - m10b) * f01b1);
        ST2(6,  f01r0, f01r1);
        ST2(7,  f01g0, f01g1);
        ST2(8,  f01b0, f01b1);
        ST2(9,  f10r0, f10r1);
        ST2(10, f10g0, f10g1);
        ST2(11, f10b0, f10b1);
        ST2(16, m01a, m01b);
        ST2(17, m10a, m10b);
#undef ST2
    }
#undef S_IN
#undef S_ER
#undef S_HM
#undef S_HX
}

__global__ void __launch_bounds__(NT, 4) open_compose_kernel(
    const int* __restrict__ kptr, float* __restrict__ out)
{
    extern __shared__ float2 Dyn2[];
    float2* BufA = Dyn2;
    float2* BufB = Dyn2 + NIN_E;

    int kk = kptr[0];
    int r = (kk >= 2) ? (kk - 1) / 2 : 0;
    if (r > RMAX) r = RMAX;

    switch (r) {
        case 0: open_body<0>(BufA, BufB, out); break;
        case 1: open_body<1>(BufA, BufB, out); break;
        case 2: open_body<2>(BufA, BufB, out); break;
        case 3: open_body<3>(BufA, BufB, out); break;
        default: open_body<4>(BufA, BufB, out); break;
    }
}

// ---------------------------------------------------------------------------
extern "C" void kernel_launch(void* const* d_in, const int* in_sizes, int n_in,
                              void* d_out, int out_size)
{
    const float* img0  = (const float*)d_in[0];
    const float* img1  = (const float*)d_in[1];
    const float* flow0 = (const float*)d_in[2];
    const float* flow1 = (const float*)d_in[3];
    const float* z0    = (const float*)d_in[4];
    const float* z1    = (const float*)d_in[5];
    const int*   kptr  = (const int*)d_in[6];
    float* out = (float*)d_out;

    static cudaStream_t s1 = nullptr, sC = nullptr;
    static cudaEvent_t evFork = nullptr, evM0 = nullptr, evM1 = nullptr,
                       evJoin1 = nullptr, evJoinC = nullptr;
    if (s1 == nullptr) {
        cudaStreamCreateWithFlags(&s1, cudaStreamNonBlocking);
        cudaStreamCreateWithFlags(&sC, cudaStreamNonBlocking);
        cudaEventCreateWithFlags(&evFork, cudaEventDisableTiming);
        cudaEventCreateWithFlags(&evM0, cudaEventDisableTiming);
        cudaEventCreateWithFlags(&evM1, cudaEventDisableTiming);
        cudaEventCreateWithFlags(&evJoin1, cudaEventDisableTiming);
        cudaEventCreateWithFlags(&evJoinC, cudaEventDisableTiming);
        cudaFuncSetAttribute(open_compose_kernel,
                             cudaFuncAttributeMaxDynamicSharedMemorySize,
                             DYN_SMEM_BYTES);
    }

    void* accPtr = nullptr;
    cudaGetSymbolAddress(&accPtr, g_acc);
    const size_t dirBytes = sizeof(float) * (size_t)BB * HW * 4;
    float4* acc_d0 = reinterpret_cast<float4*>(accPtr);
    float4* acc_d1 = acc_d0 + (size_t)BB * HW;

    int threads = 256;
    int blocks = (NPIX + threads - 1) / threads;

    cudaEventRecord(evFork, 0);
    cudaStreamWaitEvent(s1, evFork, 0);
    cudaStreamWaitEvent(sC, evFork, 0);

    cudaMemsetAsync(acc_d0, 0, dirBytes, 0);
    cudaEventRecord(evM0, 0);
    splat_dir_kernel<<<blocks, threads, 0, 0>>>(img0, flow1, z1, acc_d0);

    cudaStreamWaitEvent(s1, evM0, 0);
    cudaMemsetAsync(acc_d1, 0, dirBytes, s1);
    cudaEventRecord(evM1, s1);
    splat_dir_kernel<<<blocks, threads, 0, s1>>>(img1, flow0, z0, acc_d1);
    cudaEventRecord(evJoin1, s1);

    cudaStreamWaitEvent(sC, evM1, 0);
    {
        int fblocks = (FQ + threads - 1) / threads;
        flow_copy_kernel<<<fblocks, threads, 0, sC>>>(
            reinterpret_cast<const float4*>(flow0),
            reinterpret_cast<const float4*>(flow1),
            reinterpret_cast<float4*>(out));
        cudaEventRecord(evJoinC, sC);
    }

    cudaStreamWaitEvent(0, evJoin1, 0);
    dim3 gblk(TBX, TTY, 1);
    dim3 ggrid(WW / TPX, HH / TTY, BB);
    open_compose_kernel<<<ggrid, gblk, DYN_SMEM_BYTES, 0>>>(kptr, out);

    cudaStreamWaitEvent(0, evJoinC, 0);
}

// round 16
// speedup vs baseline: 1.0140x; 1.0140x over previous
#include <cuda_runtime.h>
#include <math.h>

#define BB 2
#define HH 720
#define WW 1280
#define HW (HH*WW)
#define NPIX (BB*HW)
#define EPSF 1e-7f

// Scratch: splat accumulators [dir][b][pixel][4ch]  (~59 MB)
__device__ __align__(16) float g_acc[(size_t)2 * BB * HW * 4];

// ---------------------------------------------------------------------------
// Splat kernel, ONE direction per launch (1 px/thread — measured REDG floor).
// ---------------------------------------------------------------------------
__global__ void __launch_bounds__(256) splat_dir_kernel(
    const float* __restrict__ img, const float* __restrict__ fl,
    const float* __restrict__ zz, float4* __restrict__ accBase)
{
    int i = blockIdx.x * blockDim.x + threadIdx.x;
    if (i >= NPIX) return;
    int b = i / HW;
    int p = i - b * HW;
    int y = p / WW;
    int x = p - y * WW;

    float fx = (float)x + 0.5f * fl[(size_t)(b * 2 + 1) * HW + p];
    float fy = (float)y + 0.5f * fl[(size_t)(b * 2 + 0) * HW + p];
    float w  = __expf(zz[(size_t)b * HW + p]);
    float vr = img[(size_t)(b * 3 + 0) * HW + p] * w;
    float vg = img[(size_t)(b * 3 + 1) * HW + p] * w;
    float vb = img[(size_t)(b * 3 + 2) * HW + p] * w;

    float x0f = floorf(fx), y0f = floorf(fy);
    int ix0 = (int)x0f, iy0 = (int)y0f;
    float ax = fx - x0f, ay = fy - y0f;

    float4* acc = accBase + (size_t)b * HW;
#pragma unroll
    for (int cy = 0; cy < 2; ++cy) {
        int ty = iy0 + cy;
        if ((unsigned)ty >= (unsigned)HH) continue;
        float wy = cy ? ay : (1.0f - ay);
#pragma unroll
        for (int cx = 0; cx < 2; ++cx) {
            int tx = ix0 + cx;
            if ((unsigned)tx >= (unsigned)WW) continue;
            float wt = wy * (cx ? ax : (1.0f - ax));
            atomicAdd(acc + ((size_t)ty * WW + tx),
                      make_float4(vr * wt, vg * wt, vb * wt, w * wt));
        }
    }
}

// ---------------------------------------------------------------------------
// Flow channels (12-15): out = 0.5 * flow. DRAM-bound; hidden under splats.
// ---------------------------------------------------------------------------
#define FQ (BB * 2 * HW / 4)
__global__ void __launch_bounds__(256) flow_copy_kernel(
    const float4* __restrict__ f0, const float4* __restrict__ f1,
    float4* __restrict__ out)
{
    int i = blockIdx.x * blockDim.x + threadIdx.x;
    if (i >= FQ) return;
    const int CH4 = HW / 4;
    int b = i / (2 * CH4);
    int rem = i - b * (2 * CH4);
    int c = rem / CH4;
    int p4 = rem - c * CH4;

    float4 q0 = __ldcs(f0 + i);
    float4 q1 = __ldcs(f1 + i);
    float4 h0 = make_float4(0.5f*q0.x, 0.5f*q0.y, 0.5f*q0.z, 0.5f*q0.w);
    float4 h1 = make_float4(0.5f*q1.x, 0.5f*q1.y, 0.5f*q1.z, 0.5f*q1.w);
    __stcs(out + (size_t)(b * 18 + 12 + c) * CH4 + p4, h0);
    __stcs(out + (size_t)(b * 18 + 14 + c) * CH4 + p4, h1);
}

// ---------------------------------------------------------------------------
// Fused normalize + morphological open + compose (R14 structure).
// 64x16 px tile, 32x16 threads, 2 px/thread (x-pairs), float2 stores.
// Buffer overlay: BufA: s_in (st 1-2) -> s_er (st 3-4);
//                 BufB: s_hm (st 2-3) -> s_hx (st 4-5).
// Stage 1b enumerates the halo RING directly (no skipped center iterations).
// 38.9KB dyn smem, 4 blocks/SM, regs clamped to 32.
// ---------------------------------------------------------------------------
#define TPX 64
#define TBX 32
#define TTY 16
#define RMAX 4
#define NT (TBX * TTY)   // 512

#define NIN_F (2 * (TTY + 4 * RMAX) * (TPX + 4 * RMAX))  // 5120 floats
#define NHM_F (2 * (TTY + 4 * RMAX) * (TPX + 2 * RMAX))  // 4608 floats
#define DYN_SMEM_BYTES ((NIN_F + NHM_F) * (int)sizeof(float))   // 38912 B

template<int R>
__device__ __forceinline__ void open_body(
    float* __restrict__ BufA, float* __restrict__ BufB,
    float* __restrict__ out)
{
    constexpr int INW = TPX + 4 * R;
    constexpr int INH = TTY + 4 * R;
    constexpr int HMW = TPX + 2 * R;   // even
    constexpr int EH  = TTY + 2 * R;   // even
    constexpr int WIN = 2 * R;

    const float PINF = __int_as_float(0x7f800000);
    const float NINF = __int_as_float(0xff800000);

    int b  = blockIdx.z;
    int ox = blockIdx.x * TPX;
    int oy = blockIdx.y * TTY;
    int tid = threadIdx.y * TBX + threadIdx.x;
    int txx = threadIdx.x, tyy = threadIdx.y;

#define S_IN(m, iy, ix) BufA[(m) * (INH * INW) + (iy) * INW + (ix)]
#define S_ER(m, ey, hx) BufA[(m) * (EH * HMW) + (ey) * HMW + (hx)]
#define S_HM(m, iy, hx) BufB[(m) * (INH * HMW) + (iy) * HMW + (hx)]
#define S_HX(m, ey, xx) BufB[(m) * (EH * TPX) + (ey) * TPX + (xx)]

    int gx0 = ox + 2 * txx;
    int gy  = oy + tyy;
    size_t p0 = (size_t)gy * WW + gx0;

    const float* w0 = g_acc + ((size_t)(0 * BB + b) * HW << 2) + 3;
    const float* w1 = g_acc + ((size_t)(1 * BB + b) * HW << 2) + 3;

    // Stage 1a: center w values from direct scalar loads (2 px, 2 masks)
    {
        int cy = tyy + 2 * R, cx = 2 * txx + 2 * R;
        S_IN(0, cy, cx)     = w0[p0 << 2];
        S_IN(0, cy, cx + 1) = w0[(p0 + 1) << 2];
        S_IN(1, cy, cx)     = w1[p0 << 2];
        S_IN(1, cy, cx + 1) = w1[(p0 + 1) << 2];
    }

    // Stage 1b: halo RING enumerated directly; +inf outside image
    if (R > 0) {
        constexpr int TB   = 2 * R * INW;      // top band count (= bottom)
        constexpr int LR   = TTY * 2 * R;      // left band count (= right)
        constexpr int RING = 2 * TB + 2 * LR;
        for (int idx = tid; idx < RING; idx += NT) {
            int iy, ix;
            if (idx < TB) {                    // top band
                iy = idx / INW;
                ix = idx - iy * INW;
            } else if (idx < 2 * TB) {         // bottom band
                int j = idx - TB;
                iy = TTY + 2 * R + j / INW;
                ix = j - (j / INW) * INW;
            } else if (idx < 2 * TB + LR) {    // left band
                int j = idx - 2 * TB;
                iy = 2 * R + j / (2 * R);
                ix = j - (j / (2 * R)) * (2 * R);
            } else {                           // right band
                int j = idx - 2 * TB - LR;
                iy = 2 * R + j / (2 * R);
                ix = TPX + 2 * R + (j - (j / (2 * R)) * (2 * R));
            }
            int hy = oy - 2 * R + iy;
            int hx = ox - 2 * R + ix;
            float v0 = PINF, v1 = PINF;
            if ((unsigned)hy < (unsigned)HH && (unsigned)hx < (unsigned)WW) {
                size_t o = ((size_t)hy * WW + hx) << 2;
                v0 = w0[o];
                v1 = w1[o];
            }
            S_IN(0, iy, ix) = v0;
            S_IN(1, iy, ix) = v1;
        }
    }
    __syncthreads();

    // Stage 2: horizontal min, paired outputs (reads s_in, writes s_hm)
    {
        constexpr int HMW2 = HMW / 2;
        for (int idx = tid; idx < INH * HMW2; idx += NT) {
            int iy = idx / HMW2;
            int hx = (idx - iy * HMW2) * 2;
            float c0 = S_IN(0, iy, hx + 1);
            float c1 = S_IN(1, iy, hx + 1);
#pragma unroll
            for (int dd = 2; dd <= WIN; ++dd) {
                c0 = fminf(c0, S_IN(0, iy, hx + dd));
                c1 = fminf(c1, S_IN(1, iy, hx + dd));
            }
            S_HM(0, iy, hx)     = fminf(S_IN(0, iy, hx), c0);
            S_HM(1, iy, hx)     = fminf(S_IN(1, iy, hx), c1);
            S_HM(0, iy, hx + 1) = fminf(c0, S_IN(0, iy, hx + WIN + 1));
            S_HM(1, iy, hx + 1) = fminf(c1, S_IN(1, iy, hx + WIN + 1));
        }
    }
    __syncthreads();   // s_in dead -> BufA reusable as s_er

    // Stage 3: vertical min -> erosion (reads s_hm, writes s_er); OOB -> -inf
    {
        constexpr int EH2 = EH / 2;
        for (int idx = tid; idx < EH2 * HMW; idx += NT) {
            int ep = idx / HMW;
            int hx = idx - ep * HMW;
            int ey = ep * 2;
            int hgx = ox - R + hx;
            bool colok = (unsigned)hgx < (unsigned)WW;
            int hy0 = oy - R + ey;
            float c0 = S_HM(0, ey + 1, hx);
            float c1 = S_HM(1, ey + 1, hx);
#pragma unroll
            for (int dd = 2; dd <= WIN; ++dd) {
                c0 = fminf(c0, S_HM(0, ey + dd, hx));
                c1 = fminf(c1, S_HM(1, ey + dd, hx));
            }
            bool ok0 = colok && ((unsigned)hy0 < (unsigned)HH);
            bool ok1 = colok && ((unsigned)(hy0 + 1) < (unsigned)HH);
            S_ER(0, ey, hx)     = ok0 ? fminf(S_HM(0, ey, hx), c0) : NINF;
            S_ER(1, ey, hx)     = ok0 ? fminf(S_HM(1, ey, hx), c1) : NINF;
            S_ER(0, ey + 1, hx) = ok1 ? fminf(c0, S_HM(0, ey + WIN + 1, hx)) : NINF;
            S_ER(1, ey + 1, hx) = ok1 ? fminf(c1, S_HM(1, ey + WIN + 1, hx)) : NINF;
        }
    }
    __syncthreads();   // s_hm dead -> BufB reusable as s_hx

    // Stage 4: horizontal max (reads s_er, writes s_hx)
    {
        constexpr int TPX2 = TPX / 2;
        for (int idx = tid; idx < EH * TPX2; idx += NT) {
            int ey = idx / TPX2;
            int xx = (idx - ey * TPX2) * 2;
            float c0 = S_ER(0, ey, xx + 1);
            float c1 = S_ER(1, ey, xx + 1);
#pragma unroll
            for (int dd = 2; dd <= WIN; ++dd) {
                c0 = fmaxf(c0, S_ER(0, ey, xx + dd));
                c1 = fmaxf(c1, S_ER(1, ey, xx + dd));
            }
            S_HX(0, ey, xx)     = fmaxf(S_ER(0, ey, xx), c0);
            S_HX(1, ey, xx)     = fmaxf(S_ER(1, ey, xx), c1);
            S_HX(0, ey, xx + 1) = fmaxf(c0, S_ER(0, ey, xx + WIN + 1));
            S_HX(1, ey, xx + 1) = fmaxf(c1, S_ER(1, ey, xx + WIN + 1));
        }
    }
    __syncthreads();

    // Stage 5: vertical max; f(w)=w/(w+eps); normalize centers; compose.
    {
        float wa = S_HX(0, tyy, 2 * txx), wb = S_HX(0, tyy, 2 * txx + 1);
        float wc = S_HX(1, tyy, 2 * txx), wd = S_HX(1, tyy, 2 * txx + 1);
#pragma unroll
        for (int dd = 1; dd <= WIN; ++dd) {
            wa = fmaxf(wa, S_HX(0, tyy + dd, 2 * txx));
            wb = fmaxf(wb, S_HX(0, tyy + dd, 2 * txx + 1));
            wc = fmaxf(wc, S_HX(1, tyy + dd, 2 * txx));
            wd = fmaxf(wd, S_HX(1, tyy + dd, 2 * txx + 1));
        }
        float m01a = wa / (wa + EPSF), m01b = wb / (wb + EPSF);
        float m10a = wc / (wc + EPSF), m10b = wd / (wd + EPSF);

        const float4* acc0 = reinterpret_cast<const float4*>(g_acc) + (size_t)(0 * BB + b) * HW;
        const float4* acc1 = reinterpret_cast<const float4*>(g_acc) + (size_t)(1 * BB + b) * HW;
        float4 a0a = acc0[p0], a0b = acc0[p0 + 1];
        float4 a1a = acc1[p0], a1b = acc1[p0 + 1];
        float i0a = 1.0f / (a0a.w + EPSF), i0b = 1.0f / (a0b.w + EPSF);
        float i1a = 1.0f / (a1a.w + EPSF), i1b = 1.0f / (a1b.w + EPSF);

        float f01r0 = a0a.x * i0a, f01r1 = a0b.x * i0b;
        float f01g0 = a0a.y * i0a, f01g1 = a0b.y * i0b;
        float f01b0 = a0a.z * i0a, f01b1 = a0b.z * i0b;
        float f10r0 = a1a.x * i1a, f10r1 = a1b.x * i1b;
        float f10g0 = a1a.y * i1a, f10g1 = a1b.y * i1b;
        float f10b0 = a1a.z * i1a, f10b1 = a1b.z * i1b;

        float* ob = out + (size_t)b * 18 * HW;
#define ST2(c, v0, v1) __stcs(reinterpret_cast<float2*>(&ob[(size_t)(c) * HW + p0]), make_float2(v0, v1))
        ST2(0,  m01a * f01r0 + (1.0f - m01a) * f10r0, m01b * f01r1 + (1.0f - m01b) * f10r1);
        ST2(1,  m01a * f01g0 + (1.0f - m01a) * f10g0, m01b * f01g1 + (1.0f - m01b) * f10g1);
        ST2(2,  m01a * f01b0 + (1.0f - m01a) * f10b0, m01b * f01b1 + (1.0f - m01b) * f10b1);
        ST2(3,  m10a * f10r0 + (1.0f - m10a) * f01r0, m10b * f10r1 + (1.0f - m10b) * f01r1);
        ST2(4,  m10a * f10g0 + (1.0f - m10a) * f01g0, m10b * f10g1 + (1.0f - m10b) * f01g1);
        ST2(5,  m10a * f10b0 + (1.0f - m10a) * f01b0, m10b * f10b1 + (1.0f - m10b) * f01b1);
        ST2(6,  f01r0, f01r1);
        ST2(7,  f01g0, f01g1);
        ST2(8,  f01b0, f01b1);
        ST2(9,  f10r0, f10r1);
        ST2(10, f10g0, f10g1);
        ST2(11, f10b0, f10b1);
        ST2(16, m01a, m01b);
        ST2(17, m10a, m10b);
#undef ST2
    }
#undef S_IN
#undef S_ER
#undef S_HM
#undef S_HX
}

__global__ void __launch_bounds__(NT, 4) open_compose_kernel(
    const int* __restrict__ kptr, float* __restrict__ out)
{
    extern __shared__ float Dyn[];
    float* BufA = Dyn;
    float* BufB = Dyn + NIN_F;

    int kk = kptr[0];
    int r = (kk >= 2) ? (kk - 1) / 2 : 0;
    if (r > RMAX) r = RMAX;

    switch (r) {
        case 0: open_body<0>(BufA, BufB, out); break;
        case 1: open_body<1>(BufA, BufB, out); break;
        case 2: open_body<2>(BufA, BufB, out); break;
        case 3: open_body<3>(BufA, BufB, out); break;
        default: open_body<4>(BufA, BufB, out); break;
    }
}

// ---------------------------------------------------------------------------
extern "C" void kernel_launch(void* const* d_in, const int* in_sizes, int n_in,
                              void* d_out, int out_size)
{
    const float* img0  = (const float*)d_in[0];
    const float* img1  = (const float*)d_in[1];
    const float* flow0 = (const float*)d_in[2];
    const float* flow1 = (const float*)d_in[3];
    const float* z0    = (const float*)d_in[4];
    const float* z1    = (const float*)d_in[5];
    const int*   kptr  = (const int*)d_in[6];
    float* out = (float*)d_out;

    static cudaStream_t s1 = nullptr, sC = nullptr;
    static cudaEvent_t evFork = nullptr, evM0 = nullptr, evM1 = nullptr,
                       evJoin1 = nullptr, evJoinC = nullptr;
    if (s1 == nullptr) {
        cudaStreamCreateWithFlags(&s1, cudaStreamNonBlocking);
        cudaStreamCreateWithFlags(&sC, cudaStreamNonBlocking);
        cudaEventCreateWithFlags(&evFork, cudaEventDisableTiming);
        cudaEventCreateWithFlags(&evM0, cudaEventDisableTiming);
        cudaEventCreateWithFlags(&evM1, cudaEventDisableTiming);
        cudaEventCreateWithFlags(&evJoin1, cudaEventDisableTiming);
        cudaEventCreateWithFlags(&evJoinC, cudaEventDisableTiming);
        cudaFuncSetAttribute(open_compose_kernel,
                             cudaFuncAttributeMaxDynamicSharedMemorySize,
                             DYN_SMEM_BYTES);
    }

    void* accPtr = nullptr;
    cudaGetSymbolAddress(&accPtr, g_acc);
    const size_t dirBytes = sizeof(float) * (size_t)BB * HW * 4;
    float4* acc_d0 = reinterpret_cast<float4*>(accPtr);
    float4* acc_d1 = acc_d0 + (size_t)BB * HW;

    int threads = 256;
    int blocks = (NPIX + threads - 1) / threads;

    cudaEventRecord(evFork, 0);
    cudaStreamWaitEvent(s1, evFork, 0);
    cudaStreamWaitEvent(sC, evFork, 0);

    cudaMemsetAsync(acc_d0, 0, dirBytes, 0);
    cudaEventRecord(evM0, 0);
    splat_dir_kernel<<<blocks, threads, 0, 0>>>(img0, flow1, z1, acc_d0);

    cudaStreamWaitEvent(s1, evM0, 0);
    cudaMemsetAsync(acc_d1, 0, dirBytes, s1);
    cudaEventRecord(evM1, s1);
    splat_dir_kernel<<<blocks, threads, 0, s1>>>(img1, flow0, z0, acc_d1);
    cudaEventRecord(evJoin1, s1);

    cudaStreamWaitEvent(sC, evM1, 0);
    {
        int fblocks = (FQ + threads - 1) / threads;
        flow_copy_kernel<<<fblocks, threads, 0, sC>>>(
            reinterpret_cast<const float4*>(flow0),
            reinterpret_cast<const float4*>(flow1),
            reinterpret_cast<float4*>(out));
        cudaEventRecord(evJoinC, sC);
    }

    cudaStreamWaitEvent(0, evJoin1, 0);
    dim3 gblk(TBX, TTY, 1);
    dim3 ggrid(WW / TPX, HH / TTY, BB);
    open_compose_kernel<<<ggrid, gblk, DYN_SMEM_BYTES, 0>>>(kptr, out);

    cudaStreamWaitEvent(0, evJoinC, 0);
}